// round 5
// baseline (speedup 1.0000x reference)
#include <cuda_runtime.h>
#include <math.h>

// Problem constants (fixed shapes from reference setup_inputs)
#define Bc 16
#define Hc 50
#define Sc 256
#define Dc 256
#define Kc 32
#define SM1 255            // S-1 valid slots after dropping s=0
#define EPSf 1e-12f

// Output layout: [ps_terms (B,H*K,D) | ps_term_mask (B,H*K) | kid (B,H,K) as float]
#define OFF_MASK ((size_t)Bc * Hc * Kc * Dc)            // 6,553,600
#define OFF_KID  (OFF_MASK + (size_t)Bc * Hc * Kc)      // 6,579,200

__device__ __forceinline__ float warp_sum(float v) {
#pragma unroll
    for (int o = 16; o > 0; o >>= 1) v += __shfl_xor_sync(0xffffffffu, v, o);
    return v;
}

__device__ __forceinline__ float4 ldcs4(const float4* p) {
    return __ldcs(p);
}

__global__ __launch_bounds__(256)
void matching_reducer_kernel(
    const float* __restrict__ sel,    // news_selection_embedding (B,H,S,D)
    const float* __restrict__ txt,    // news_embedding           (B,H,S,D)
    const float* __restrict__ user,   // user_repr                (B,1,D)
    const float* __restrict__ amask,  // his_attn_mask            (B,H,S)
    const int*   __restrict__ rmask,  // his_refined_mask         (B,H,S) int32
    const float* __restrict__ seg,    // segment_embedding        (H,1,D)
    float* __restrict__ out)
{
    const int bh   = blockIdx.x;          // 0 .. B*H-1
    const int b    = bh / Hc;
    const int h    = bh % Hc;
    const int t    = threadIdx.x;
    const int lane = t & 31;
    const int warp = t >> 5;

    __shared__ float q[Dc];
    __shared__ float sgm[Dc];
    __shared__ float scores[SM1 + 1];
    __shared__ float red[8];
    __shared__ int   topidx[Kc];
    __shared__ float topw[Kc];
    __shared__ float s_invq;

    // Stage q (user vector) and segment row into smem
    q[t]   = user[(size_t)b * Dc + t];
    sgm[t] = seg[(size_t)h * Dc + t];
    __syncthreads();

    // ---- 1/max(||q||, eps) ----
    {
        float v = q[t] * q[t];
        v = warp_sum(v);
        if (lane == 0) red[warp] = v;
        __syncthreads();
        if (t == 0) {
            float s = 0.f;
#pragma unroll
            for (int i = 0; i < 8; i++) s += red[i];
            s_invq = 1.0f / fmaxf(sqrtf(s), EPSf);
        }
        __syncthreads();
    }
    const float invq = s_invq;

    // q vector held in registers per lane (2 float4 = 8 floats covers D=256 / 32 lanes)
    const float4* q4  = (const float4*)q;
    const float4  qv0 = q4[lane];
    const float4  qv1 = q4[lane + 32];

    // ---- cosine scores for 255 rows (skip s=0), 2 rows per warp-iteration ----
    const float*  selb = sel + (size_t)bh * Sc * Dc + Dc;   // row s -> original s+1
    const int*    rm   = rmask + (size_t)bh * Sc + 1;

    for (int s = warp; s < SM1; s += 16) {
        const int  s1    = s + 8;
        const bool have1 = (s1 < SM1);

        const float4* row0 = (const float4*)(selb + (size_t)s * Dc);
        const float4* row1 = (const float4*)(selb + (size_t)(have1 ? s1 : s) * Dc);

        // issue all 4 global loads up-front (MLP=4 per lane)
        float4 a00 = ldcs4(row0 + lane);
        float4 a01 = ldcs4(row0 + lane + 32);
        float4 a10 = ldcs4(row1 + lane);
        float4 a11 = ldcs4(row1 + lane + 32);

        float dot0 = a00.x * qv0.x + a00.y * qv0.y + a00.z * qv0.z + a00.w * qv0.w
                   + a01.x * qv1.x + a01.y * qv1.y + a01.z * qv1.z + a01.w * qv1.w;
        float nrm0 = a00.x * a00.x + a00.y * a00.y + a00.z * a00.z + a00.w * a00.w
                   + a01.x * a01.x + a01.y * a01.y + a01.z * a01.z + a01.w * a01.w;
        float dot1 = a10.x * qv0.x + a10.y * qv0.y + a10.z * qv0.z + a10.w * qv0.w
                   + a11.x * qv1.x + a11.y * qv1.y + a11.z * qv1.z + a11.w * qv1.w;
        float nrm1 = a10.x * a10.x + a10.y * a10.y + a10.z * a10.z + a10.w * a10.w
                   + a11.x * a11.x + a11.y * a11.y + a11.z * a11.z + a11.w * a11.w;

        dot0 = warp_sum(dot0);
        nrm0 = warp_sum(nrm0);
        dot1 = warp_sum(dot1);
        nrm1 = warp_sum(nrm1);

        if (lane == 0) {
            float sc0  = dot0 * invq / fmaxf(sqrtf(nrm0), EPSf);
            bool  v0   = (s < Kc) || (rm[s] != 0);
            scores[s]  = v0 ? sc0 : -INFINITY;
            if (have1) {
                float sc1  = dot1 * invq / fmaxf(sqrtf(nrm1), EPSf);
                bool  v1   = (s1 < Kc) || (rm[s1] != 0);
                scores[s1] = v1 ? sc1 : -INFINITY;
            }
        }
    }
    __syncthreads();

    // ---- top-K: single-warp, register-resident, zero block barriers ----
    // Lane l owns keys for scores l*8 .. l*8+7 (lane 31 slot 7 = pad, key 0).
    // Key = (monotone-float(score) << 32) | (SM1-1-s): max key => score desc, index asc.
    if (warp == 0) {
        unsigned long long key[8];
#pragma unroll
        for (int j = 0; j < 8; j++) {
            int s = lane * 8 + j;
            if (s < SM1) {
                unsigned int fu = __float_as_uint(scores[s]);
                unsigned int o  = fu ^ ((fu >> 31) ? 0xFFFFFFFFu : 0x80000000u);
                key[j] = ((unsigned long long)o << 32) | (unsigned int)(SM1 - 1 - s);
            } else {
                key[j] = 0ull;   // pad, never selected (>=32 finite scores exist)
            }
        }

        unsigned long long mykey = 0ull;   // lane k keeps the k-th selected key
        for (int k = 0; k < Kc; k++) {
            // local argmax over this lane's 8 keys
            unsigned long long m = key[0]; int mj = 0;
#pragma unroll
            for (int j = 1; j < 8; j++) if (key[j] > m) { m = key[j]; mj = j; }
            // warp max
            unsigned long long w = m;
#pragma unroll
            for (int off = 16; off > 0; off >>= 1) {
                unsigned long long o = __shfl_xor_sync(0xffffffffu, w, off);
                if (o > w) w = o;
            }
            if (m == w) key[mj] = 0ull;    // unique owner removes it (indices distinct)
            if (lane == k) mykey = w;
        }

        // decode lane's selected entry
        int idx = SM1 - 1 - (int)(mykey & 0xFFFFFFFFu);
        unsigned int o  = (unsigned int)(mykey >> 32);
        unsigned int fu = (o >> 31) ? (o ^ 0x80000000u) : (o ^ 0xFFFFFFFFu);
        float sc = __uint_as_float(fu);

        // softmax over the 32 selected scores (lane 0 holds the max)
        float mx = __shfl_sync(0xffffffffu, sc, 0);
        float e  = expf(sc - mx);
        float s  = warp_sum(e);

        topidx[lane] = idx;
        topw[lane]   = e / s;
    }
    __syncthreads();

    // ---- gather + scale + segment add ----
    const float*  txtb = txt + (size_t)bh * Sc * Dc + Dc;
    float4*       outb = (float4*)(out + (size_t)(b * Hc + h) * Kc * Dc);
    const float4* sg4  = (const float4*)sgm;
    const float4  sv0  = sg4[lane];
    const float4  sv1  = sg4[lane + 32];

    for (int k = warp; k < Kc; k += 8) {
        const int   idx = topidx[k];
        const float w   = topw[k];
        const float4* row = (const float4*)(txtb + (size_t)idx * Dc);
        float4*       o4  = outb + (size_t)k * (Dc / 4);

        float4 a0 = ldcs4(row + lane);
        float4 a1 = ldcs4(row + lane + 32);

        float4 r0, r1;
        r0.x = a0.x * w + sv0.x;  r0.y = a0.y * w + sv0.y;
        r0.z = a0.z * w + sv0.z;  r0.w = a0.w * w + sv0.w;
        r1.x = a1.x * w + sv1.x;  r1.y = a1.y * w + sv1.y;
        r1.z = a1.z * w + sv1.z;  r1.w = a1.w * w + sv1.w;

        __stcs(o4 + lane,      r0);
        __stcs(o4 + lane + 32, r1);
    }

    // ---- mask + kid outputs ----
    if (t < Kc) {
        const size_t oidx = (size_t)(b * Hc + h) * Kc + t;
        const int    idx  = topidx[t];
        out[OFF_MASK + oidx] = amask[(size_t)bh * Sc + 1 + idx];
        out[OFF_KID + oidx]  = (float)idx;
    }
}

extern "C" void kernel_launch(void* const* d_in, const int* in_sizes, int n_in,
                              void* d_out, int out_size)
{
    (void)in_sizes; (void)n_in; (void)out_size;
    const float* sel   = (const float*)d_in[0];
    const float* txt   = (const float*)d_in[1];
    const float* user  = (const float*)d_in[2];
    // d_in[3] = news_repr (unused by reference)
    const float* amask = (const float*)d_in[4];
    const int*   rmask = (const int*)d_in[5];
    const float* seg   = (const float*)d_in[6];
    float* out = (float*)d_out;

    matching_reducer_kernel<<<Bc * Hc, 256>>>(sel, txt, user, amask, rmask, seg, out);
}

// round 6
// speedup vs baseline: 1.4058x; 1.4058x over previous
#include <cuda_runtime.h>
#include <math.h>

// Problem constants (fixed shapes from reference setup_inputs)
#define Bc 16
#define Hc 50
#define Sc 256
#define Dc 256
#define Kc 32
#define SM1 255            // S-1 valid slots after dropping s=0
#define EPSf 1e-12f

// Output layout: [ps_terms (B,H*K,D) | ps_term_mask (B,H*K) | kid (B,H,K) as float]
#define OFF_MASK ((size_t)Bc * Hc * Kc * Dc)            // 6,553,600
#define OFF_KID  (OFF_MASK + (size_t)Bc * Hc * Kc)      // 6,579,200

typedef unsigned long long u64;
typedef unsigned int u32;

__device__ __forceinline__ float warp_sum(float v) {
#pragma unroll
    for (int o = 16; o > 0; o >>= 1) v += __shfl_xor_sync(0xffffffffu, v, o);
    return v;
}

__device__ __forceinline__ float4 ldcs4(const float4* p) { return __ldcs(p); }

// Bitonic compare-exchange across lanes: partner at xor-distance j.
// keepMaxLow: lanes with (lane & j)==0 keep the larger value.
__device__ __forceinline__ u64 bitonic_ce(u64 k, int j, bool keepMaxLow, int lane) {
    u64 o = __shfl_xor_sync(0xffffffffu, k, j);
    u64 mx = (k > o) ? k : o;
    u64 mn = (k > o) ? o : k;
    bool low = ((lane & j) == 0);
    return (low == keepMaxLow) ? mx : mn;
}

__global__ __launch_bounds__(256)
void matching_reducer_kernel(
    const float* __restrict__ sel,    // news_selection_embedding (B,H,S,D)
    const float* __restrict__ txt,    // news_embedding           (B,H,S,D)
    const float* __restrict__ user,   // user_repr                (B,1,D)
    const float* __restrict__ amask,  // his_attn_mask            (B,H,S)
    const int*   __restrict__ rmask,  // his_refined_mask         (B,H,S) int32
    const float* __restrict__ seg,    // segment_embedding        (H,1,D)
    float* __restrict__ out)
{
    const int bh   = blockIdx.x;          // 0 .. B*H-1
    const int b    = bh / Hc;
    const int h    = bh % Hc;
    const int t    = threadIdx.x;
    const int lane = t & 31;
    const int warp = t >> 5;

    __shared__ float q[Dc];
    __shared__ float sgm[Dc];
    __shared__ float scores[SM1 + 1];
    __shared__ float red[8];
    __shared__ u64   mbuf[14][32];        // merge staging: [0..7] sorted, [8..11] L1, [12..13] L2
    __shared__ int   topidx[Kc];
    __shared__ float topw[Kc];
    __shared__ float s_invq;

    // Stage q (user vector) and segment row into smem
    q[t]   = user[(size_t)b * Dc + t];
    sgm[t] = seg[(size_t)h * Dc + t];
    __syncthreads();

    // ---- 1/max(||q||, eps) ----
    {
        float v = q[t] * q[t];
        v = warp_sum(v);
        if (lane == 0) red[warp] = v;
        __syncthreads();
        if (t == 0) {
            float s = 0.f;
#pragma unroll
            for (int i = 0; i < 8; i++) s += red[i];
            s_invq = 1.0f / fmaxf(sqrtf(s), EPSf);
        }
        __syncthreads();
    }
    const float invq = s_invq;

    // ---- cosine scores for 255 rows (skip s=0), 2 rows per warp-iteration (MLP=4) ----
    const float*  selb = sel + (size_t)bh * Sc * Dc + Dc;   // row s -> original s+1
    const int*    rm   = rmask + (size_t)bh * Sc + 1;
    const float4* q4   = (const float4*)q;

    for (int s = warp; s < SM1; s += 16) {
        const int  s1    = s + 8;
        const bool have1 = (s1 < SM1);

        const float4* row0 = (const float4*)(selb + (size_t)s * Dc);
        const float4* row1 = (const float4*)(selb + (size_t)(have1 ? s1 : s) * Dc);

        // issue all 4 global loads up-front
        float4 a00 = ldcs4(row0 + lane);
        float4 a01 = ldcs4(row0 + lane + 32);
        float4 a10 = ldcs4(row1 + lane);
        float4 a11 = ldcs4(row1 + lane + 32);

        float4 qv0 = q4[lane];
        float4 qv1 = q4[lane + 32];

        float dot0 = a00.x * qv0.x + a00.y * qv0.y + a00.z * qv0.z + a00.w * qv0.w
                   + a01.x * qv1.x + a01.y * qv1.y + a01.z * qv1.z + a01.w * qv1.w;
        float nrm0 = a00.x * a00.x + a00.y * a00.y + a00.z * a00.z + a00.w * a00.w
                   + a01.x * a01.x + a01.y * a01.y + a01.z * a01.z + a01.w * a01.w;
        float dot1 = a10.x * qv0.x + a10.y * qv0.y + a10.z * qv0.z + a10.w * qv0.w
                   + a11.x * qv1.x + a11.y * qv1.y + a11.z * qv1.z + a11.w * qv1.w;
        float nrm1 = a10.x * a10.x + a10.y * a10.y + a10.z * a10.z + a10.w * a10.w
                   + a11.x * a11.x + a11.y * a11.y + a11.z * a11.z + a11.w * a11.w;

        dot0 = warp_sum(dot0);
        nrm0 = warp_sum(nrm0);
        dot1 = warp_sum(dot1);
        nrm1 = warp_sum(nrm1);

        if (lane == 0) {
            float sc0  = dot0 * invq / fmaxf(sqrtf(nrm0), EPSf);
            bool  v0   = (s < Kc) || (rm[s] != 0);
            scores[s]  = v0 ? sc0 : -INFINITY;
            if (have1) {
                float sc1  = dot1 * invq / fmaxf(sqrtf(nrm1), EPSf);
                bool  v1   = (s1 < Kc) || (rm[s1] != 0);
                scores[s1] = v1 ? sc1 : -INFINITY;
            }
        }
    }
    __syncthreads();

    // ---- top-K: parallel bitonic sort+merge across all 8 warps ----
    // Key = (monotone-float(score) << 32) | (SM1-1-s): larger key => higher score,
    // ties broken toward smaller s. Exact full ordering -> matches jax top_k.
    {
        // each warp sorts its 32-slot segment (warp 7's slot 255 = pad key 0)
        int s = warp * 32 + lane;
        u64 key = 0ull;
        if (s < SM1) {
            u32 fu = __float_as_uint(scores[s]);
            u32 o  = fu ^ ((fu >> 31) ? 0xFFFFFFFFu : 0x80000000u);
            key = ((u64)o << 32) | (u32)(SM1 - 1 - s);
        }

        // warp bitonic sort, descending (15 compare-exchanges)
#pragma unroll
        for (int k = 2; k <= 32; k <<= 1) {
            bool desc = ((lane & k) == 0);
#pragma unroll
            for (int j = k >> 1; j >= 1; j >>= 1)
                key = bitonic_ce(key, j, desc, lane);
        }
        mbuf[warp][lane] = key;
        __syncthreads();

        // L1: 4 warps merge pairs (0,1)->(8) .. (6,7)->(11): keep top-32 of each pair
        if (warp < 4) {
            u64 a = mbuf[2 * warp][lane];
            u64 bb = mbuf[2 * warp + 1][31 - lane];
            u64 kk = (a > bb) ? a : bb;            // bitonic top-32 of the union
#pragma unroll
            for (int j = 16; j >= 1; j >>= 1)      // bitonic merge -> descending
                kk = bitonic_ce(kk, j, true, lane);
            mbuf[8 + warp][lane] = kk;
        }
        __syncthreads();

        // L2: 2 warps merge (8,9)->(12), (10,11)->(13)
        if (warp < 2) {
            u64 a = mbuf[8 + 2 * warp][lane];
            u64 bb = mbuf[8 + 2 * warp + 1][31 - lane];
            u64 kk = (a > bb) ? a : bb;
#pragma unroll
            for (int j = 16; j >= 1; j >>= 1)
                kk = bitonic_ce(kk, j, true, lane);
            mbuf[12 + warp][lane] = kk;
        }
        __syncthreads();

        // L3: warp 0 merges (12,13) -> final top-32 (descending), then softmax
        if (warp == 0) {
            u64 a = mbuf[12][lane];
            u64 bb = mbuf[13][31 - lane];
            u64 kk = (a > bb) ? a : bb;
#pragma unroll
            for (int j = 16; j >= 1; j >>= 1)
                kk = bitonic_ce(kk, j, true, lane);

            // decode lane's selected entry (lane k = k-th best)
            int idx = SM1 - 1 - (int)(kk & 0xFFFFFFFFu);
            u32 o   = (u32)(kk >> 32);
            u32 fu  = (o >> 31) ? (o ^ 0x80000000u) : (o ^ 0xFFFFFFFFu);
            float sc = __uint_as_float(fu);

            float mx = __shfl_sync(0xffffffffu, sc, 0);   // lane 0 holds the max
            float e  = expf(sc - mx);
            float ssum = warp_sum(e);

            topidx[lane] = idx;
            topw[lane]   = e / ssum;
        }
    }
    __syncthreads();

    // ---- gather + scale + segment add ----
    const float*  txtb = txt + (size_t)bh * Sc * Dc + Dc;
    float4*       outb = (float4*)(out + (size_t)(b * Hc + h) * Kc * Dc);
    const float4* sg4  = (const float4*)sgm;

    for (int k = warp; k < Kc; k += 8) {
        const int   idx = topidx[k];
        const float w   = topw[k];
        const float4* row = (const float4*)(txtb + (size_t)idx * Dc);
        float4*       o4  = outb + (size_t)k * (Dc / 4);

        float4 a0 = ldcs4(row + lane);
        float4 a1 = ldcs4(row + lane + 32);
        float4 sv0 = sg4[lane];
        float4 sv1 = sg4[lane + 32];

        float4 r0, r1;
        r0.x = a0.x * w + sv0.x;  r0.y = a0.y * w + sv0.y;
        r0.z = a0.z * w + sv0.z;  r0.w = a0.w * w + sv0.w;
        r1.x = a1.x * w + sv1.x;  r1.y = a1.y * w + sv1.y;
        r1.z = a1.z * w + sv1.z;  r1.w = a1.w * w + sv1.w;

        __stcs(o4 + lane,      r0);
        __stcs(o4 + lane + 32, r1);
    }

    // ---- mask + kid outputs ----
    if (t < Kc) {
        const size_t oidx = (size_t)(b * Hc + h) * Kc + t;
        const int    idx  = topidx[t];
        out[OFF_MASK + oidx] = amask[(size_t)bh * Sc + 1 + idx];
        out[OFF_KID + oidx]  = (float)idx;
    }
}

extern "C" void kernel_launch(void* const* d_in, const int* in_sizes, int n_in,
                              void* d_out, int out_size)
{
    (void)in_sizes; (void)n_in; (void)out_size;
    const float* sel   = (const float*)d_in[0];
    const float* txt   = (const float*)d_in[1];
    const float* user  = (const float*)d_in[2];
    // d_in[3] = news_repr (unused by reference)
    const float* amask = (const float*)d_in[4];
    const int*   rmask = (const int*)d_in[5];
    const float* seg   = (const float*)d_in[6];
    float* out = (float*)d_out;

    matching_reducer_kernel<<<Bc * Hc, 256>>>(sel, txt, user, amask, rmask, seg, out);
}